// round 1
// baseline (speedup 1.0000x reference)
#include <cuda_runtime.h>
#include <math.h>

#define B_   64
#define N_   4096
#define D_   128
#define E_   512
#define S_   8          // N-splits per batch
#define WPB  8          // warps per block (256 threads)
#define TSTREAMS (S_*WPB)   // 64 interleaved slot streams per batch

// ---- device scratch (no allocations allowed) ----
__device__ float g_q  [B_*D_];
__device__ float g_qa [B_*D_];
__device__ int   g_cnt[B_];
__device__ float g_pm [B_*S_];
__device__ float g_ps [B_*S_];
__device__ float g_pacc[B_*S_*D_];

// ============================================================
// Kernel 1: proj_q = vecQ @ Wq^T + bq ; also qa = q * Wa.
// Also decodes imagesObjectNum (robust to int32 vs int64 storage).
// grid(64), block(128): thread d computes one output element.
// ============================================================
__global__ void proj_kernel(const float* __restrict__ vq,
                            const float* __restrict__ Wq,
                            const float* __restrict__ bq,
                            const float* __restrict__ Wa,
                            const int*   __restrict__ ion)
{
    const int b = blockIdx.x;
    const int d = threadIdx.x;

    if (d == 0) {
        // Detect int64 vs int32 layout. Values are in [0, 4096), so if the
        // array is int64 (little-endian), every odd 32-bit word is 0.
        // We only read the first 256 bytes here (safe for both layouts).
        bool is64 = true;
        #pragma unroll
        for (int i = 0; i < 32; i++) {
            if (ion[2*i + 1] != 0) is64 = false;
        }
        // Reading word 2*b (up to byte 508) only happens if layout is int64,
        // in which case the allocation is 512 bytes.
        g_cnt[b] = is64 ? ion[2*b] : ion[b];
    }

    const float4* v4 = (const float4*)(vq + (size_t)b * E_);
    const float4* w4 = (const float4*)(Wq + (size_t)d * E_);
    float a0 = 0.f, a1 = 0.f, a2 = 0.f, a3 = 0.f;
    #pragma unroll 4
    for (int i = 0; i < E_/4; i += 4) {
        float4 x, y;
        x = v4[i+0]; y = w4[i+0]; a0 += x.x*y.x + x.y*y.y + x.z*y.z + x.w*y.w;
        x = v4[i+1]; y = w4[i+1]; a1 += x.x*y.x + x.y*y.y + x.z*y.z + x.w*y.w;
        x = v4[i+2]; y = w4[i+2]; a2 += x.x*y.x + x.y*y.y + x.z*y.z + x.w*y.w;
        x = v4[i+3]; y = w4[i+3]; a3 += x.x*y.x + x.y*y.y + x.z*y.z + x.w*y.w;
    }
    float q = (a0 + a1) + (a2 + a3) + bq[d];
    g_q [b*D_ + d] = q;
    g_qa[b*D_ + d] = q * Wa[d];
}

// ------------------------------------------------------------
// per-slot logit: dot(kb, q*Wa) / max(||kb*q||, eps) + ba
// warp-collective (D=128 split as float4 per lane).
// ------------------------------------------------------------
__device__ __forceinline__ float slot_raw(float4 k, float4 q, float4 qa,
                                          float ba, bool uniform)
{
    float px = k.x*q.x, py = k.y*q.y, pz = k.z*q.z, pw = k.w*q.w;
    float dot = k.x*qa.x + k.y*qa.y + k.z*qa.z + k.w*qa.w;
    float nrm = px*px + py*py + pz*pz + pw*pw;
    #pragma unroll
    for (int off = 16; off > 0; off >>= 1) {
        dot += __shfl_xor_sync(0xffffffffu, dot, off);
        nrm += __shfl_xor_sync(0xffffffffu, nrm, off);
    }
    float r = dot / fmaxf(sqrtf(nrm), 1e-12f) + ba;
    // count==0: reference gives softmax of constant -1e30 == uniform 1/N.
    // Constant raw == 0 reproduces that exactly.
    return uniform ? 0.0f : r;
}

__device__ __forceinline__ void online_update(float& m, float& s, float4& acc,
                                              float r, float4 k)
{
    float mn = fmaxf(m, r);
    float sc = __expf(m - mn);   // m starts at -3e38 -> underflows to 0, no NaN
    float w  = __expf(r - mn);
    s = s * sc + w;
    acc.x = acc.x * sc + w * k.x;
    acc.y = acc.y * sc + w * k.y;
    acc.z = acc.z * sc + w * k.z;
    acc.w = acc.w * sc + w * k.w;
    m = mn;
}

// ============================================================
// Kernel 2: single pass over kb with online softmax.
// grid(B*S) blocks, 256 threads (8 warps). Slot streams are
// interleaved (stride 64) so variable per-batch counts stay balanced.
// Masked slots (n >= count) are never read: they contribute exactly 0.
// ============================================================
__global__ void __launch_bounds__(256, 4)
att_kernel(const float* __restrict__ kb, const float* __restrict__ ba_p)
{
    const int bs    = blockIdx.x;
    const int b     = bs >> 3;          // / S_
    const int warp  = threadIdx.x >> 5;
    const int lane  = threadIdx.x & 31;
    const int split = bs & (S_ - 1);
    const int stream = split * WPB + warp;   // 0..63

    const int  cnt     = g_cnt[b];
    const int  limit   = (cnt == 0) ? N_ : cnt;
    const bool uniform = (cnt == 0);
    const float ba = __ldg(ba_p);

    const float4 q  = ((const float4*)(g_q  + b*D_))[lane];
    const float4 qa = ((const float4*)(g_qa + b*D_))[lane];
    const float4* kbB = (const float4*)(kb + (size_t)b * N_ * D_);

    float  m = -3.0e38f, s = 0.0f;
    float4 acc = make_float4(0.f, 0.f, 0.f, 0.f);

    // batches of 4 slots for MLP
    for (int n0 = stream; n0 < limit; n0 += 4 * TSTREAMS) {
        const bool v1 = (n0 + 1*TSTREAMS) < limit;
        const bool v2 = (n0 + 2*TSTREAMS) < limit;
        const bool v3 = (n0 + 3*TSTREAMS) < limit;

        float4 k0 = kbB[(size_t)(n0            ) * 32 + lane];
        float4 k1 = v1 ? kbB[(size_t)(n0 + 1*TSTREAMS) * 32 + lane] : make_float4(0,0,0,0);
        float4 k2 = v2 ? kbB[(size_t)(n0 + 2*TSTREAMS) * 32 + lane] : make_float4(0,0,0,0);
        float4 k3 = v3 ? kbB[(size_t)(n0 + 3*TSTREAMS) * 32 + lane] : make_float4(0,0,0,0);

        float r0 = slot_raw(k0, q, qa, ba, uniform);
        float r1 = slot_raw(k1, q, qa, ba, uniform);
        float r2 = slot_raw(k2, q, qa, ba, uniform);
        float r3 = slot_raw(k3, q, qa, ba, uniform);

        online_update(m, s, acc, r0, k0);
        if (v1) online_update(m, s, acc, r1, k1);
        if (v2) online_update(m, s, acc, r2, k2);
        if (v3) online_update(m, s, acc, r3, k3);
    }

    // merge the 8 warps of this CTA
    __shared__ float sm_m[WPB];
    __shared__ float sm_s[WPB];
    __shared__ float sacc[WPB][D_];

    ((float4*)sacc[warp])[lane] = acc;
    if (lane == 0) { sm_m[warp] = m; sm_s[warp] = s; }
    __syncthreads();

    if (threadIdx.x < D_) {
        const int d = threadIdx.x;
        float mM = -3.0e38f;
        #pragma unroll
        for (int w = 0; w < WPB; w++) mM = fmaxf(mM, sm_m[w]);
        float ss = 0.f, av = 0.f;
        #pragma unroll
        for (int w = 0; w < WPB; w++) {
            float sc = __expf(sm_m[w] - mM);   // (-3e38) - (-3e38) = 0 -> 1, s=0 anyway
            ss += sm_s[w] * sc;
            av += sacc[w][d] * sc;
        }
        g_pacc[bs*D_ + d] = av;
        if (d == 0) { g_pm[bs] = mM; g_ps[bs] = ss; }
    }
}

// ============================================================
// Kernel 3: merge the S_ split partials, divide, write output.
// ============================================================
__global__ void combine_kernel(float* __restrict__ out)
{
    const int b = blockIdx.x;
    const int d = threadIdx.x;
    float mM = -3.0e38f;
    #pragma unroll
    for (int i = 0; i < S_; i++) mM = fmaxf(mM, g_pm[b*S_ + i]);
    float ss = 0.f, av = 0.f;
    #pragma unroll
    for (int i = 0; i < S_; i++) {
        float sc = __expf(g_pm[b*S_ + i] - mM);
        ss += g_ps[b*S_ + i] * sc;
        av += g_pacc[(b*S_ + i)*D_ + d] * sc;
    }
    out[b*D_ + d] = av / ss;   // ss > 0 always (limit >= 1 per batch)
}

extern "C" void kernel_launch(void* const* d_in, const int* in_sizes, int n_in,
                              void* d_out, int out_size)
{
    const float* kb  = (const float*)d_in[0];
    const float* vq  = (const float*)d_in[1];
    const int*   ion = (const int*)  d_in[2];   // int32 or int64, auto-detected
    const float* Wq  = (const float*)d_in[3];
    const float* bq  = (const float*)d_in[4];
    const float* Wa  = (const float*)d_in[5];
    const float* ba  = (const float*)d_in[6];
    float* out = (float*)d_out;

    proj_kernel   <<<B_,      D_ >>>(vq, Wq, bq, Wa, ion);
    att_kernel    <<<B_ * S_, 256>>>(kb, ba);
    combine_kernel<<<B_,      D_ >>>(out);
}

// round 2
// speedup vs baseline: 1.3614x; 1.3614x over previous
#include <cuda_runtime.h>
#include <math.h>

#define B_   64
#define N_   4096
#define D_   128
#define E_   512
#define S_   16         // N-splits per batch
#define WPB  8          // warps per block (256 threads)
#define TSTREAMS (S_*WPB)   // 128 interleaved slot streams per batch

// ---- device scratch (no allocations allowed) ----
__device__ float g_q  [B_*D_];
__device__ float g_qa [B_*D_];
__device__ int   g_cnt[B_];
__device__ float g_pm [B_*S_];
__device__ float g_ps [B_*S_];
__device__ float g_pacc[B_*S_*D_];

// ============================================================
// Kernel 1: proj_q = vecQ @ Wq^T + bq ; qa = q * Wa.
// Warp-per-output: 64*128 = 8192 outputs -> 1024 blocks x 8 warps.
// Each warp: 512-MAC dot via 4 float4/lane + shuffle reduce.
// Also decodes imagesObjectNum (robust to int32 vs int64 storage).
// ============================================================
__global__ void __launch_bounds__(256)
proj_kernel(const float* __restrict__ vq,
            const float* __restrict__ Wq,
            const float* __restrict__ bq,
            const float* __restrict__ Wa,
            const int*   __restrict__ ion)
{
    const int warp = threadIdx.x >> 5;
    const int lane = threadIdx.x & 31;
    const int idx  = blockIdx.x * WPB + warp;   // 0..8191
    const int b    = idx >> 7;                  // / D_
    const int d    = idx & (D_ - 1);

    if (d == 0 && lane == 0) {
        // Detect int64 vs int32 layout. Values in [0,4096): if int64 (LE),
        // every odd 32-bit word of the first 64 words is 0. Reads stay in
        // the first 256 bytes (safe for both layouts); word 2*b (<=508B)
        // is only read when layout is int64 (alloc is 512B).
        bool is64 = true;
        #pragma unroll
        for (int i = 0; i < 32; i++)
            if (ion[2*i + 1] != 0) is64 = false;
        g_cnt[b] = is64 ? ion[2*b] : ion[b];
    }

    const float4* v4 = (const float4*)(vq + (size_t)b * E_);
    const float4* w4 = (const float4*)(Wq + (size_t)d * E_);
    float a = 0.f;
    #pragma unroll
    for (int j = 0; j < E_/4/32; j++) {            // 4 iters
        float4 x = v4[lane + j*32];
        float4 y = w4[lane + j*32];
        a += x.x*y.x + x.y*y.y + x.z*y.z + x.w*y.w;
    }
    #pragma unroll
    for (int off = 16; off > 0; off >>= 1)
        a += __shfl_xor_sync(0xffffffffu, a, off);

    if (lane == 0) {
        float q = a + bq[d];
        g_q [b*D_ + d] = q;
        g_qa[b*D_ + d] = q * Wa[d];
    }
}

// ------------------------------------------------------------
// per-slot logit: dot(kb, q*Wa) / max(||kb*q||, eps) + ba
// warp-collective (D=128 split as float4 per lane).
// ------------------------------------------------------------
__device__ __forceinline__ float slot_raw(float4 k, float4 q, float4 qa,
                                          float ba, bool uniform)
{
    float px = k.x*q.x, py = k.y*q.y, pz = k.z*q.z, pw = k.w*q.w;
    float dot = k.x*qa.x + k.y*qa.y + k.z*qa.z + k.w*qa.w;
    float nrm = px*px + py*py + pz*pz + pw*pw;
    #pragma unroll
    for (int off = 16; off > 0; off >>= 1) {
        dot += __shfl_xor_sync(0xffffffffu, dot, off);
        nrm += __shfl_xor_sync(0xffffffffu, nrm, off);
    }
    float r = dot / fmaxf(sqrtf(nrm), 1e-12f) + ba;
    // count==0: reference = softmax of constant -1e30 == uniform.
    // Constant raw == 0 reproduces that exactly.
    return uniform ? 0.0f : r;
}

__device__ __forceinline__ void online_update(float& m, float& s, float4& acc,
                                              float r, float4 k)
{
    float mn = fmaxf(m, r);
    float sc = __expf(m - mn);   // m starts at -3e38 -> underflows to 0, no NaN
    float w  = __expf(r - mn);
    s = s * sc + w;
    acc.x = acc.x * sc + w * k.x;
    acc.y = acc.y * sc + w * k.y;
    acc.z = acc.z * sc + w * k.z;
    acc.w = acc.w * sc + w * k.w;
    m = mn;
}

// ============================================================
// Kernel 2: single pass over kb with online softmax.
// grid(B*S) = 1024 blocks, 256 threads (8 warps). Slot streams
// interleaved (stride 128) so variable per-batch counts balance.
// Masked slots (n >= count) are never read: they contribute 0.
// ============================================================
__global__ void __launch_bounds__(256)
att_kernel(const float* __restrict__ kb, const float* __restrict__ ba_p)
{
    const int bs    = blockIdx.x;
    const int b     = bs >> 4;          // / S_
    const int warp  = threadIdx.x >> 5;
    const int lane  = threadIdx.x & 31;
    const int split = bs & (S_ - 1);
    const int stream = split * WPB + warp;   // 0..127

    const int  cnt     = g_cnt[b];
    const int  limit   = (cnt == 0) ? N_ : cnt;
    const bool uniform = (cnt == 0);
    const float ba = __ldg(ba_p);

    const float4 q  = ((const float4*)(g_q  + b*D_))[lane];
    const float4 qa = ((const float4*)(g_qa + b*D_))[lane];
    const float4* kbB = (const float4*)(kb + (size_t)b * N_ * D_);

    float  m = -3.0e38f, s = 0.0f;
    float4 acc = make_float4(0.f, 0.f, 0.f, 0.f);

    // batches of 4 slots for MLP
    for (int n0 = stream; n0 < limit; n0 += 4 * TSTREAMS) {
        const bool v1 = (n0 + 1*TSTREAMS) < limit;
        const bool v2 = (n0 + 2*TSTREAMS) < limit;
        const bool v3 = (n0 + 3*TSTREAMS) < limit;

        float4 k0 = kbB[(size_t)(n0            ) * 32 + lane];
        float4 k1 = v1 ? kbB[(size_t)(n0 + 1*TSTREAMS) * 32 + lane] : make_float4(0,0,0,0);
        float4 k2 = v2 ? kbB[(size_t)(n0 + 2*TSTREAMS) * 32 + lane] : make_float4(0,0,0,0);
        float4 k3 = v3 ? kbB[(size_t)(n0 + 3*TSTREAMS) * 32 + lane] : make_float4(0,0,0,0);

        float r0 = slot_raw(k0, q, qa, ba, uniform);
        float r1 = slot_raw(k1, q, qa, ba, uniform);
        float r2 = slot_raw(k2, q, qa, ba, uniform);
        float r3 = slot_raw(k3, q, qa, ba, uniform);

        online_update(m, s, acc, r0, k0);
        if (v1) online_update(m, s, acc, r1, k1);
        if (v2) online_update(m, s, acc, r2, k2);
        if (v3) online_update(m, s, acc, r3, k3);
    }

    // merge the 8 warps of this CTA
    __shared__ float sm_m[WPB];
    __shared__ float sm_s[WPB];
    __shared__ float sacc[WPB][D_];

    ((float4*)sacc[warp])[lane] = acc;
    if (lane == 0) { sm_m[warp] = m; sm_s[warp] = s; }
    __syncthreads();

    if (threadIdx.x < D_) {
        const int d = threadIdx.x;
        float mM = -3.0e38f;
        #pragma unroll
        for (int w = 0; w < WPB; w++) mM = fmaxf(mM, sm_m[w]);
        float ss = 0.f, av = 0.f;
        #pragma unroll
        for (int w = 0; w < WPB; w++) {
            float sc = __expf(sm_m[w] - mM);   // empty warp: s=0 anyway
            ss += sm_s[w] * sc;
            av += sacc[w][d] * sc;
        }
        g_pacc[bs*D_ + d] = av;
        if (d == 0) { g_pm[bs] = mM; g_ps[bs] = ss; }
    }
}

// ============================================================
// Kernel 3: merge the S_ split partials, divide, write output.
// ============================================================
__global__ void combine_kernel(float* __restrict__ out)
{
    const int b = blockIdx.x;
    const int d = threadIdx.x;
    float mM = -3.0e38f;
    #pragma unroll
    for (int i = 0; i < S_; i++) mM = fmaxf(mM, g_pm[b*S_ + i]);
    float ss = 0.f, av = 0.f;
    #pragma unroll
    for (int i = 0; i < S_; i++) {
        float sc = __expf(g_pm[b*S_ + i] - mM);
        ss += g_ps[b*S_ + i] * sc;
        av += g_pacc[(b*S_ + i)*D_ + d] * sc;
    }
    out[b*D_ + d] = av / ss;   // ss > 0 always (limit >= 1 per batch)
}

extern "C" void kernel_launch(void* const* d_in, const int* in_sizes, int n_in,
                              void* d_out, int out_size)
{
    const float* kb  = (const float*)d_in[0];
    const float* vq  = (const float*)d_in[1];
    const int*   ion = (const int*)  d_in[2];   // int32 or int64, auto-detected
    const float* Wq  = (const float*)d_in[3];
    const float* bq  = (const float*)d_in[4];
    const float* Wa  = (const float*)d_in[5];
    const float* ba  = (const float*)d_in[6];
    float* out = (float*)d_out;

    proj_kernel   <<<B_ * D_ / WPB, 256>>>(vq, Wq, bq, Wa, ion);
    att_kernel    <<<B_ * S_,       256>>>(kb, ba);
    combine_kernel<<<B_,            D_ >>>(out);
}

// round 3
// speedup vs baseline: 1.8003x; 1.3224x over previous
#include <cuda_runtime.h>
#include <math.h>

#define B_   64
#define N_   4096
#define D_   128
#define E_   512
#define S_   16                 // N-splits per batch
#define GPB  32                 // 8-lane groups per block (256 thr)
#define TSTREAMS (S_*GPB)       // 512 interleaved slot streams per batch

// ---- device scratch (no allocations allowed) ----
__device__ float g_q  [B_*D_];
__device__ float g_qa [B_*D_];
__device__ int   g_cnt[B_];
__device__ float g_M;           // >= max logit (Cauchy-Schwarz bound)
__device__ float g_ba;
__device__ float g_ps [B_*S_];
__device__ float g_pacc[B_*S_*D_];

// ============================================================
// Kernel 1: proj_q = vecQ @ Wq^T + bq ; qa = q * Wa.
// 2 warps per output (split-K), 4 outputs per 256-thr block.
// Side duties: decode imagesObjectNum; compute M = max(ba+||Wa||,0).
// ============================================================
__global__ void __launch_bounds__(256)
proj_kernel(const float* __restrict__ vq,
            const float* __restrict__ Wq,
            const float* __restrict__ bq,
            const float* __restrict__ Wa,
            const float* __restrict__ ba_p,
            const int*   __restrict__ ion)
{
    __shared__ float sp[8];
    const int warp = threadIdx.x >> 5;
    const int lane = threadIdx.x & 31;
    const int out_local = warp >> 1;     // 0..3
    const int half = warp & 1;           // K half
    const int idx = blockIdx.x * 4 + out_local;  // 0..8191
    const int b = idx >> 7;
    const int d = idx & (D_ - 1);

    const float4* v4 = (const float4*)(vq + (size_t)b * E_) + half * 64;
    const float4* w4 = (const float4*)(Wq + (size_t)d * E_) + half * 64;
    float4 x0 = v4[lane*2], x1 = v4[lane*2+1];
    float4 y0 = w4[lane*2], y1 = w4[lane*2+1];
    float a = x0.x*y0.x + x0.y*y0.y + x0.z*y0.z + x0.w*y0.w
            + x1.x*y1.x + x1.y*y1.y + x1.z*y1.z + x1.w*y1.w;
    #pragma unroll
    for (int off = 16; off > 0; off >>= 1)
        a += __shfl_xor_sync(0xffffffffu, a, off);
    if (lane == 0) sp[warp] = a;
    __syncthreads();

    if (threadIdx.x < 4) {
        int idx2 = blockIdx.x * 4 + threadIdx.x;
        int d2 = idx2 & (D_ - 1);
        float qv = sp[2*threadIdx.x] + sp[2*threadIdx.x + 1] + bq[d2];
        g_q [idx2] = qv;
        g_qa[idx2] = qv * Wa[d2];
    }

    // side duty A: decode imagesObjectNum (int32 vs int64 robust)
    if (blockIdx.x == 0 && warp == 7 && lane == 0) {
        // Values in [0,4096): if int64 (LE), every odd word of first 64 is 0.
        // Reads stay within first 256B until mode known; word 2*b (<=508B)
        // read only when layout is int64 (alloc is 512B).
        bool is64 = true;
        #pragma unroll
        for (int i = 0; i < 32; i++)
            if (ion[2*i + 1] != 0) is64 = false;
        for (int bb = 0; bb < B_; bb++)
            g_cnt[bb] = is64 ? ion[2*bb] : ion[bb];
    }
    // side duty B: M = max(ba + ||Wa||, 0)  (upper bound on all logits)
    if (blockIdx.x == 1 && warp == 7) {
        float t = 0.f;
        #pragma unroll
        for (int i = 0; i < 4; i++) {
            float wv = Wa[i*32 + lane];
            t += wv * wv;
        }
        #pragma unroll
        for (int off = 16; off > 0; off >>= 1)
            t += __shfl_xor_sync(0xffffffffu, t, off);
        if (lane == 0) {
            float ba = *ba_p;
            g_ba = ba;
            g_M  = fmaxf(ba + sqrtf(t), 0.f);
        }
    }
}

// ============================================================
// Kernel 2: single pass over kb, fixed-reference softmax weights.
// 8-lane groups: each group owns one slot (128 floats = 16/lane).
// No online-max: w = exp(L - M), pure accumulation (no serial chain).
// grid(B*S_) = 1024 blocks x 256 threads; streams interleaved
// (stride 512) so variable per-batch counts stay balanced.
// Masked slots (n >= count) are never read.
// ============================================================
__global__ void __launch_bounds__(256)
att_kernel(const float* __restrict__ kb)
{
    const int bs    = blockIdx.x;
    const int b     = bs >> 4;          // / S_
    const int split = bs & (S_ - 1);
    const int warp  = threadIdx.x >> 5;
    const int lane  = threadIdx.x & 31;
    const int g     = lane >> 3;        // group within warp (0..3)
    const int sub   = lane & 7;         // lane within group
    const int gid   = warp * 4 + g;     // 0..31

    const int  cnt     = g_cnt[b];
    const int  limit   = (cnt == 0) ? N_ : cnt;
    const bool uniform = (cnt == 0);
    const float M  = g_M;
    const float ba = g_ba;

    // q,qa: this lane's 16 floats (elements i*32 + sub*4 .. +3)
    float4 q[4], qa[4];
    #pragma unroll
    for (int i = 0; i < 4; i++) {
        q[i]  = ((const float4*)(g_q  + b*D_))[i*8 + sub];
        qa[i] = ((const float4*)(g_qa + b*D_))[i*8 + sub];
    }

    const float4* kb4 = (const float4*)(kb + (size_t)b * N_ * D_);

    float  s = 0.f;
    float4 acc[4] = {make_float4(0,0,0,0), make_float4(0,0,0,0),
                     make_float4(0,0,0,0), make_float4(0,0,0,0)};
    const float4 ZERO = make_float4(0,0,0,0);

    // two slots per group per iteration for MLP
    for (int n0 = split*GPB + gid; __any_sync(0xffffffffu, n0 < limit);
         n0 += 2*TSTREAMS) {
        const int  n1 = n0 + TSTREAMS;
        const bool v0 = n0 < limit;
        const bool v1 = n1 < limit;

        float4 k0[4], k1[4];
        #pragma unroll
        for (int i = 0; i < 4; i++)
            k0[i] = v0 ? kb4[(size_t)n0*32 + i*8 + sub] : ZERO;
        #pragma unroll
        for (int i = 0; i < 4; i++)
            k1[i] = v1 ? kb4[(size_t)n1*32 + i*8 + sub] : ZERO;

        #pragma unroll
        for (int t = 0; t < 2; t++) {
            float4* k = t ? k1 : k0;
            bool    v = t ? v1 : v0;
            float dot = 0.f, nrm = 0.f;
            #pragma unroll
            for (int i = 0; i < 4; i++) {
                float px = k[i].x*q[i].x, py = k[i].y*q[i].y;
                float pz = k[i].z*q[i].z, pw = k[i].w*q[i].w;
                nrm += px*px + py*py + pz*pz + pw*pw;
                dot += k[i].x*qa[i].x + k[i].y*qa[i].y
                     + k[i].z*qa[i].z + k[i].w*qa[i].w;
            }
            #pragma unroll
            for (int off = 4; off > 0; off >>= 1) {
                dot += __shfl_xor_sync(0xffffffffu, dot, off);
                nrm += __shfl_xor_sync(0xffffffffu, nrm, off);
            }
            float L = uniform ? 0.f
                              : (dot / fmaxf(sqrtf(nrm), 1e-12f) + ba);
            float w = v ? __expf(L - M) : 0.f;   // L <= M always: no overflow
            s += w;
            #pragma unroll
            for (int i = 0; i < 4; i++) {
                acc[i].x += w * k[i].x;  acc[i].y += w * k[i].y;
                acc[i].z += w * k[i].z;  acc[i].w += w * k[i].w;
            }
        }
    }

    // merge 32 groups of this CTA (plain sums; 528B row stride stays 16B-aligned)
    __shared__ float sacc[GPB][132];
    __shared__ float ssum[GPB];
    #pragma unroll
    for (int i = 0; i < 4; i++)
        *(float4*)&sacc[gid][i*32 + sub*4] = acc[i];
    if (sub == 0) ssum[gid] = s;
    __syncthreads();

    if (threadIdx.x < D_) {
        const int d = threadIdx.x;
        float a = 0.f;
        #pragma unroll
        for (int j = 0; j < GPB; j++) a += sacc[j][d];
        g_pacc[bs*D_ + d] = a;
    } else if (threadIdx.x == D_) {
        float t = 0.f;
        #pragma unroll
        for (int j = 0; j < GPB; j++) t += ssum[j];
        g_ps[bs] = t;
    }
}

// ============================================================
// Kernel 3: sum the S_ split partials, divide, write output.
// ============================================================
__global__ void combine_kernel(float* __restrict__ out)
{
    const int b = blockIdx.x;
    const int d = threadIdx.x;
    float ss = 0.f, av = 0.f;
    #pragma unroll
    for (int i = 0; i < S_; i++) {
        ss += g_ps[b*S_ + i];
        av += g_pacc[(b*S_ + i)*D_ + d];
    }
    out[b*D_ + d] = av / ss;   // ss > 0 always (limit >= 1)
}

extern "C" void kernel_launch(void* const* d_in, const int* in_sizes, int n_in,
                              void* d_out, int out_size)
{
    const float* kb  = (const float*)d_in[0];
    const float* vq  = (const float*)d_in[1];
    const int*   ion = (const int*)  d_in[2];   // int32 or int64, auto-detected
    const float* Wq  = (const float*)d_in[3];
    const float* bq  = (const float*)d_in[4];
    const float* Wa  = (const float*)d_in[5];
    const float* ba  = (const float*)d_in[6];
    float* out = (float*)d_out;

    proj_kernel   <<<B_ * D_ / 4, 256>>>(vq, Wq, bq, Wa, ba, ion);
    att_kernel    <<<B_ * S_,     256>>>(kb);
    combine_kernel<<<B_,          D_ >>>(out);
}